// round 1
// baseline (speedup 1.0000x reference)
#include <cuda_runtime.h>

#define BDIM   128
#define CH     32
#define OB     64
#define BBLK   32
#define KSPLIT 16
#define BATCH  256
#define HID    512
#define DIN    2048

// ---- device scratch (no allocations allowed) ----
__device__ float g_r[HID * DIN];              // 4 MB: 1/(scale+eps)
__device__ float g_c[HID * DIN];              // 4 MB: -t * r
__device__ float g_part[KSPLIT * BATCH * HID];// 8 MB split-K partials
__device__ float g_f1[BATCH * HID];
__device__ float g_f2[BATCH * HID];

// ---- per-layer param transform: r = 1/(A_MIN + softplus(s) + 1e-8), c = -t*r ----
__global__ void prep_kernel(const float* __restrict__ t,
                            const float* __restrict__ sraw, int n) {
    int i = blockIdx.x * blockDim.x + threadIdx.x;
    if (i < n) {
        float sp = log1pf(expf(sraw[i]));
        float rr = 1.0f / (0.001f + sp + 1e-8f);
        g_r[i] = rr;
        g_c[i] = -t[i] * rr;
    }
}

// ---- main wavelet contraction: z_part[k][b][o] = sum_{i in chunk} w*(1-u)*exp(-u/2) ----
// finsel: 0 -> use fin ptr (layer 0 input x), 1 -> g_f1, 2 -> g_f2
__global__ __launch_bounds__(BDIM) void wav_kernel(const float* __restrict__ fin,
                                                   const float* __restrict__ w,
                                                   int I, int chunkI, int finsel) {
    __shared__ float xs[CH][BBLK];
    __shared__ float rs[CH][OB];
    __shared__ float cs[CH][OB];
    __shared__ float ws[CH][OB];

    const float* f = (finsel == 1) ? g_f1 : (finsel == 2) ? g_f2 : fin;

    const int tid = threadIdx.x;
    const int og = tid & 15;      // 16 o-groups of 4
    const int bg = tid >> 4;      // 8  b-groups of 4
    const int o0 = blockIdx.x * OB;
    const int b0 = blockIdx.y * BBLK;
    const int i0base = blockIdx.z * chunkI;

    float acc[4][4];
#pragma unroll
    for (int a = 0; a < 4; a++)
#pragma unroll
        for (int b = 0; b < 4; b++) acc[a][b] = 0.0f;

    // staging-load index maps
    const int xb = tid >> 2;            // 0..31 (b row)
    const int xj = (tid & 3) * 8;       // 0,8,16,24 (i offset)
    const int ol = tid >> 1;            // 0..63 (o row)
    const int oj = (tid & 1) * 16;      // 0,16 (i offset)

    const float* xrow = f + (size_t)(b0 + xb) * I + xj;
    const float* rrow = g_r + (size_t)(o0 + ol) * I + oj;
    const float* crow = g_c + (size_t)(o0 + ol) * I + oj;
    const float* wrow = w   + (size_t)(o0 + ol) * I + oj;

    for (int ic = 0; ic < chunkI; ic += CH) {
        const int i0 = i0base + ic;

        // stage x tile [CH][32], transposed
        {
            float4 v0 = *(const float4*)(xrow + i0);
            float4 v1 = *(const float4*)(xrow + i0 + 4);
            xs[xj + 0][xb] = v0.x; xs[xj + 1][xb] = v0.y;
            xs[xj + 2][xb] = v0.z; xs[xj + 3][xb] = v0.w;
            xs[xj + 4][xb] = v1.x; xs[xj + 5][xb] = v1.y;
            xs[xj + 6][xb] = v1.z; xs[xj + 7][xb] = v1.w;
        }
        // stage params [CH][64], transposed
#pragma unroll
        for (int q = 0; q < 4; q++) {
            float4 rv = *(const float4*)(rrow + i0 + q * 4);
            rs[oj + q * 4 + 0][ol] = rv.x; rs[oj + q * 4 + 1][ol] = rv.y;
            rs[oj + q * 4 + 2][ol] = rv.z; rs[oj + q * 4 + 3][ol] = rv.w;
            float4 cv = *(const float4*)(crow + i0 + q * 4);
            cs[oj + q * 4 + 0][ol] = cv.x; cs[oj + q * 4 + 1][ol] = cv.y;
            cs[oj + q * 4 + 2][ol] = cv.z; cs[oj + q * 4 + 3][ol] = cv.w;
            float4 wv = *(const float4*)(wrow + i0 + q * 4);
            ws[oj + q * 4 + 0][ol] = wv.x; ws[oj + q * 4 + 1][ol] = wv.y;
            ws[oj + q * 4 + 2][ol] = wv.z; ws[oj + q * 4 + 3][ol] = wv.w;
        }
        __syncthreads();

#pragma unroll 4
        for (int i = 0; i < CH; i++) {
            float4 x4 = *(const float4*)&xs[i][bg * 4];
            float4 r4 = *(const float4*)&rs[i][og * 4];
            float4 c4 = *(const float4*)&cs[i][og * 4];
            float4 w4 = *(const float4*)&ws[i][og * 4];
            float xa[4] = {x4.x, x4.y, x4.z, x4.w};
            float ra[4] = {r4.x, r4.y, r4.z, r4.w};
            float ca[4] = {c4.x, c4.y, c4.z, c4.w};
            float wa[4] = {w4.x, w4.y, w4.z, w4.w};
#pragma unroll
            for (int oo = 0; oo < 4; oo++) {
#pragma unroll
                for (int bb = 0; bb < 4; bb++) {
                    float s = fmaf(xa[bb], ra[oo], ca[oo]);
                    float u = s * s;
                    float g = u * -0.72134752044448170368f; // -0.5*log2(e)
                    float e;
                    asm("ex2.approx.ftz.f32 %0, %1;" : "=f"(e) : "f"(g));
                    float p = fmaf(-u, wa[oo], wa[oo]);      // w*(1-u)
                    acc[bb][oo] = fmaf(p, e, acc[bb][oo]);
                }
            }
        }
        __syncthreads();
    }

    float* dst = g_part + (size_t)blockIdx.z * (BATCH * HID)
               + (size_t)(b0 + bg * 4) * HID + o0 + og * 4;
#pragma unroll
    for (int bb = 0; bb < 4; bb++) {
        float4 st = make_float4(acc[bb][0], acc[bb][1], acc[bb][2], acc[bb][3]);
        *(float4*)(dst + (size_t)bb * HID) = st;
    }
}

// ---- split-K reduce + SiLU + LayerNorm (+ optional classifier) ----
// outsel: 1 -> write g_f1, 2 -> write g_f2, 0 -> classifier into out
__global__ __launch_bounds__(128) void reduce_kernel(const float* __restrict__ gamma,
                                                     const float* __restrict__ beta,
                                                     const float* __restrict__ cw,
                                                     const float* __restrict__ cb,
                                                     float* __restrict__ out,
                                                     int outsel) {
    const int b = blockIdx.x;
    const int tid = threadIdx.x;
    const int wid = tid >> 5, lane = tid & 31;
    __shared__ float s1[4], s2[4];

    float v[4];
    float lsum = 0.0f, lsq = 0.0f;
#pragma unroll
    for (int q = 0; q < 4; q++) {
        int o = tid + q * 128;
        float z = 0.0f;
#pragma unroll
        for (int k = 0; k < KSPLIT; k++)
            z += g_part[(size_t)k * (BATCH * HID) + (size_t)b * HID + o];
        float sig = 1.0f / (1.0f + __expf(-z));
        float a = z * sig;
        v[q] = a;
        lsum += a;
        lsq = fmaf(a, a, lsq);
    }
#pragma unroll
    for (int off = 16; off; off >>= 1) {
        lsum += __shfl_xor_sync(0xffffffffu, lsum, off);
        lsq  += __shfl_xor_sync(0xffffffffu, lsq, off);
    }
    if (lane == 0) { s1[wid] = lsum; s2[wid] = lsq; }
    __syncthreads();
    float tsum = s1[0] + s1[1] + s1[2] + s1[3];
    float tsq  = s2[0] + s2[1] + s2[2] + s2[3];
    float mean = tsum * (1.0f / HID);
    float var  = tsq * (1.0f / HID) - mean * mean;
    float rstd = rsqrtf(var + 1e-5f);

    float d0 = 0.0f, d1 = 0.0f;
    float* fout = (outsel == 1) ? g_f1 : g_f2;
#pragma unroll
    for (int q = 0; q < 4; q++) {
        int o = tid + q * 128;
        float y = (v[q] - mean) * rstd * gamma[o] + beta[o];
        if (outsel == 0) {
            d0 = fmaf(y, cw[o], d0);
            d1 = fmaf(y, cw[HID + o], d1);
        } else {
            fout[(size_t)b * HID + o] = y;
        }
    }
    if (outsel == 0) {
#pragma unroll
        for (int off = 16; off; off >>= 1) {
            d0 += __shfl_xor_sync(0xffffffffu, d0, off);
            d1 += __shfl_xor_sync(0xffffffffu, d1, off);
        }
        __syncthreads();
        if (lane == 0) { s1[wid] = d0; s2[wid] = d1; }
        __syncthreads();
        if (tid == 0) {
            out[b * 2 + 0] = s1[0] + s1[1] + s1[2] + s1[3] + cb[0];
            out[b * 2 + 1] = s2[0] + s2[1] + s2[2] + s2[3] + cb[1];
        }
    }
}

extern "C" void kernel_launch(void* const* d_in, const int* in_sizes, int n_in,
                              void* d_out, int out_size) {
    const float* x  = (const float*)d_in[0];
    const float* t0 = (const float*)d_in[1];
    const float* s0 = (const float*)d_in[2];
    const float* w0 = (const float*)d_in[3];
    const float* g0 = (const float*)d_in[4];
    const float* b0 = (const float*)d_in[5];
    const float* t1 = (const float*)d_in[6];
    const float* s1 = (const float*)d_in[7];
    const float* w1 = (const float*)d_in[8];
    const float* g1 = (const float*)d_in[9];
    const float* b1 = (const float*)d_in[10];
    const float* t2 = (const float*)d_in[11];
    const float* s2 = (const float*)d_in[12];
    const float* w2 = (const float*)d_in[13];
    const float* g2 = (const float*)d_in[14];
    const float* b2 = (const float*)d_in[15];
    const float* cw = (const float*)d_in[16];
    const float* cb = (const float*)d_in[17];
    float* out = (float*)d_out;

    dim3 gmain(HID / OB, BATCH / BBLK, KSPLIT); // (8, 8, 16) = 1024 blocks
    const int n0 = HID * DIN;                   // layer 0 params
    const int n1 = HID * HID;                   // layer 1/2 params

    // layer 0
    prep_kernel<<<(n0 + 255) / 256, 256>>>(t0, s0, n0);
    wav_kernel<<<gmain, BDIM>>>(x, w0, DIN, DIN / KSPLIT, 0);
    reduce_kernel<<<BATCH, 128>>>(g0, b0, cw, cb, out, 1);

    // layer 1
    prep_kernel<<<(n1 + 255) / 256, 256>>>(t1, s1, n1);
    wav_kernel<<<gmain, BDIM>>>(nullptr, w1, HID, HID / KSPLIT, 1);
    reduce_kernel<<<BATCH, 128>>>(g1, b1, cw, cb, out, 2);

    // layer 2 (+ classifier)
    prep_kernel<<<(n1 + 255) / 256, 256>>>(t2, s2, n1);
    wav_kernel<<<gmain, BDIM>>>(nullptr, w2, HID, HID / KSPLIT, 2);
    reduce_kernel<<<BATCH, 128>>>(g2, b2, cw, cb, out, 0);
}